// round 9
// baseline (speedup 1.0000x reference)
#include <cuda_runtime.h>
#include <stdint.h>

// N=100000, W=32, D=32. Output row = 1088 floats = 272 float4.
// Per row i: [ gathered x rows (256 f4) | dis (8 f4) | angle (8 f4) ]
// Warp handles FOUR rows: all idx + tail loads front-batched, gathers
// processed as two 2-row pairs (idx for pair B prefetched -> its gather
// chain has no exposed idx latency).

#define ROW_F4 272

__global__ __launch_bounds__(256)
void fused_gather_concat_warp4_kernel(const float4* __restrict__ x4,
                                      const void*  __restrict__ idx,
                                      const float4* __restrict__ dis4,
                                      const float4* __restrict__ ang4,
                                      float4* __restrict__ out4,
                                      int n_rows)
{
    const int warp_id = (blockIdx.x * blockDim.x + threadIdx.x) >> 5;
    const int lane    = threadIdx.x & 31;

    // Dtype detection (values < 100000: little-endian int64 => all odd
    // 32-bit words are 0; 32 random i32 all-zero: p ~ 1e-160). Broadcast.
    const int probe = __ldg((const int*)idx + 2 * lane + 1);
    const bool is64 = (__ballot_sync(0xffffffffu, probe != 0) == 0u);

    const int i0 = warp_id * 4;
    if (i0 >= n_rows) return;
    const bool has1 = (i0 + 1 < n_rows);
    const bool has2 = (i0 + 2 < n_rows);
    const bool has3 = (i0 + 3 < n_rows);

    // ── Front batch: 4 idx loads + 2 tail loads, all independent ──
    int j0, j1 = 0, j2 = 0, j3 = 0;
    if (is64) {
        const long long* idx64 = (const long long*)idx;
        j0 = (int)__ldcs(idx64 + (long long)i0 * 32 + lane);
        if (has1) j1 = (int)__ldcs(idx64 + (long long)(i0 + 1) * 32 + lane);
        if (has2) j2 = (int)__ldcs(idx64 + (long long)(i0 + 2) * 32 + lane);
        if (has3) j3 = (int)__ldcs(idx64 + (long long)(i0 + 3) * 32 + lane);
    } else {
        const int* idx32 = (const int*)idx;
        j0 = __ldcs(idx32 + i0 * 32 + lane);
        if (has1) j1 = __ldcs(idx32 + (i0 + 1) * 32 + lane);
        if (has2) j2 = __ldcs(idx32 + (i0 + 2) * 32 + lane);
        if (has3) j3 = __ldcs(idx32 + (i0 + 3) * 32 + lane);
    }

    // Tail payload: tv0 covers rows i0/i0+1 (lanes 0-15 / 16-31),
    //               tv1 covers rows i0+2/i0+3.
    const int lr = lane & 15;
    float4 tv0, tv1;
    {
        const int liA = (lane < 16) ? i0 : i0 + 1;
        if (lane < 16 || has1) {
            if (lr < 8) tv0 = __ldcs(dis4 + liA * 8 + lr);
            else        tv0 = __ldcs(ang4 + liA * 8 + (lr - 8));
        }
        const int liB = (lane < 16) ? i0 + 2 : i0 + 3;
        if ((lane < 16 && has2) || has3) {
            if (lr < 8) tv1 = __ldcs(dis4 + liB * 8 + lr);
            else        tv1 = __ldcs(ang4 + liB * 8 + (lr - 8));
        }
    }

    const int wbase = lane >> 3;   // lane-group (0..3)
    const int seg   = lane & 7;    // float4 within the 32-float x row

    // ── Pair A: rows i0, i0+1 ──
    {
        int jwa[8], jwb[8];
#pragma unroll
        for (int it = 0; it < 8; it++) {
            jwa[it] = __shfl_sync(0xffffffffu, j0, it * 4 + wbase);
            jwb[it] = __shfl_sync(0xffffffffu, j1, it * 4 + wbase);
        }
        float4 va[8], vb[8];
#pragma unroll
        for (int it = 0; it < 8; it++)
            va[it] = __ldcg(x4 + (long long)jwa[it] * 8 + seg);
        if (has1) {
#pragma unroll
            for (int it = 0; it < 8; it++)
                vb[it] = __ldcg(x4 + (long long)jwb[it] * 8 + seg);
        }
        float4* __restrict__ o0 = out4 + (long long)i0 * ROW_F4;
#pragma unroll
        for (int it = 0; it < 8; it++)
            __stcs(o0 + it * 32 + lane, va[it]);
        if (lane < 16) __stcs(o0 + 256 + lane, tv0);
        if (has1) {
            float4* __restrict__ o1 = out4 + (long long)(i0 + 1) * ROW_F4;
#pragma unroll
            for (int it = 0; it < 8; it++)
                __stcs(o1 + it * 32 + lane, vb[it]);
            if (lane >= 16) __stcs(o1 + 256 + (lane - 16), tv0);
        }
    }

    // ── Pair B: rows i0+2, i0+3 (idx already resident -> no idx latency) ──
    if (has2) {
        int jwa[8], jwb[8];
#pragma unroll
        for (int it = 0; it < 8; it++) {
            jwa[it] = __shfl_sync(0xffffffffu, j2, it * 4 + wbase);
            jwb[it] = __shfl_sync(0xffffffffu, j3, it * 4 + wbase);
        }
        float4 va[8], vb[8];
#pragma unroll
        for (int it = 0; it < 8; it++)
            va[it] = __ldcg(x4 + (long long)jwa[it] * 8 + seg);
        if (has3) {
#pragma unroll
            for (int it = 0; it < 8; it++)
                vb[it] = __ldcg(x4 + (long long)jwb[it] * 8 + seg);
        }
        float4* __restrict__ o2 = out4 + (long long)(i0 + 2) * ROW_F4;
#pragma unroll
        for (int it = 0; it < 8; it++)
            __stcs(o2 + it * 32 + lane, va[it]);
        if (lane < 16) __stcs(o2 + 256 + lane, tv1);
        if (has3) {
            float4* __restrict__ o3 = out4 + (long long)(i0 + 3) * ROW_F4;
#pragma unroll
            for (int it = 0; it < 8; it++)
                __stcs(o3 + it * 32 + lane, vb[it]);
            if (lane >= 16) __stcs(o3 + 256 + (lane - 16), tv1);
        }
    }
}

extern "C" void kernel_launch(void* const* d_in, const int* in_sizes, int n_in,
                              void* d_out, int out_size)
{
    const float4* x4   = (const float4*)d_in[0];
    const void*   idx  = d_in[1];
    const float4* dis4 = (const float4*)d_in[2];
    const float4* ang4 = (const float4*)d_in[3];
    float4* out4 = (float4*)d_out;

    const int n_rows = in_sizes[0] / 32;   // N

    const int threads = 256;                        // 8 warps/block
    const int rows_per_block = 32;                  // 4 rows per warp
    const int blocks = (n_rows + rows_per_block - 1) / rows_per_block;
    fused_gather_concat_warp4_kernel<<<blocks, threads>>>(x4, idx, dis4, ang4,
                                                          out4, n_rows);
}